// round 2
// baseline (speedup 1.0000x reference)
#include <cuda_runtime.h>
#include <cstdint>

// Problem constants (fixed by the reference)
#define BATCH    64
#define LSEQ     16384
#define FCH      128
#define KW       16
#define OUT_LEN  16369           // (16384 - 16) + 1
#define TILE_O   128             // output positions per block
#define NTHREADS 256             // 8 warps
#define O_GROUPS 4               // tid>>6 selects o-subrange
#define O_PER_GROUP (TILE_O / O_GROUPS)   // 32

// ---------------- packed f32x2 helpers (Blackwell) ----------------
__device__ __forceinline__ unsigned long long pack2(float lo, float hi) {
    unsigned long long r;
    asm("mov.b64 %0, {%1, %2};" : "=l"(r) : "f"(lo), "f"(hi));
    return r;
}
__device__ __forceinline__ void ffma2(unsigned long long& d,
                                      unsigned long long a,
                                      unsigned long long b,
                                      unsigned long long c) {
    asm("fma.rn.f32x2 %0, %1, %2, %3;" : "=l"(d) : "l"(a), "l"(b), "l"(c));
}
__device__ __forceinline__ void unpack2(unsigned long long v, float& lo, float& hi) {
    asm("mov.b64 {%0, %1}, %2;" : "=f"(lo), "=f"(hi) : "l"(v));
}

__global__ __launch_bounds__(NTHREADS, 4)
void speccnn1d_kernel(const float* __restrict__ x,
                      const float* __restrict__ kern,
                      float* __restrict__ out) {
    // x window pre-duplicated as {v,v} u64 so the mainloop is pure
    // broadcast-LDS.64 -> fma.rn.f32x2.
    __shared__ unsigned long long xs2[TILE_O + KW];      // 144 * 8B

    const int tid = threadIdx.x;
    const int b   = blockIdx.y;
    const int o0  = blockIdx.x * TILE_O;

    // ---- stage x window duplicated: xs2[i] = {x[o0+i], x[o0+i]} ----
    {
        const float* xb = x + (size_t)b * LSEQ;
        int i = tid;
        if (i < TILE_O + KW - 1) {                       // 143 elements
            int xi = o0 + i;
            float v = (xi < LSEQ) ? __ldg(&xb[xi]) : 0.0f;
            xs2[i] = pack2(v, v);
        }
    }

    // Thread -> (channel pair, o-subgroup) mapping.
    // Warp-uniform og => all xs2 reads are broadcast (conflict-free).
    const int f0 = ((tid & 31) << 1) + (((tid >> 5) & 1) << 6);  // 0..126 even
    const int og = tid >> 6;                                     // 0..3

    // ---- hoist this thread's 2 weight rows into 16 packed pairs ----
    // kern is [128][16] row-major; rows f0 and f0+1.
    unsigned long long w[KW];
    {
        const float4* r0 = reinterpret_cast<const float4*>(kern + (size_t)f0 * KW);
        const float4* r1 = reinterpret_cast<const float4*>(kern + (size_t)(f0 + 1) * KW);
        #pragma unroll
        for (int q = 0; q < 4; q++) {
            float4 a = __ldg(&r0[q]);
            float4 c = __ldg(&r1[q]);
            w[q * 4 + 0] = pack2(a.x, c.x);
            w[q * 4 + 1] = pack2(a.y, c.y);
            w[q * 4 + 2] = pack2(a.z, c.z);
            w[q * 4 + 3] = pack2(a.w, c.w);
        }
    }
    __syncthreads();

    float* outb = out + (size_t)b * OUT_LEN * FCH;

    // ---- each thread computes 32 o positions, 4 at a time ----
    #pragma unroll
    for (int jb = 0; jb < O_PER_GROUP; jb += 4) {
        const int lo = og * O_PER_GROUP + jb;            // local o within tile
        const int o  = o0 + lo;

        unsigned long long a0 = 0ull, a1 = 0ull, a2 = 0ull, a3 = 0ull;

        #pragma unroll
        for (int k = 0; k < KW; k++) {
            unsigned long long wk = w[k];
            ffma2(a0, xs2[lo + k],     wk, a0);
            ffma2(a1, xs2[lo + k + 1], wk, a1);
            ffma2(a2, xs2[lo + k + 2], wk, a2);
            ffma2(a3, xs2[lo + k + 3], wk, a3);
        }

        float v0, v1;
        if (o < OUT_LEN) {
            unpack2(a0, v0, v1);
            float2 r; r.x = fmaxf(v0, 0.0f); r.y = fmaxf(v1, 0.0f);
            *reinterpret_cast<float2*>(&outb[(size_t)o * FCH + f0]) = r;
        }
        if (o + 1 < OUT_LEN) {
            unpack2(a1, v0, v1);
            float2 r; r.x = fmaxf(v0, 0.0f); r.y = fmaxf(v1, 0.0f);
            *reinterpret_cast<float2*>(&outb[(size_t)(o + 1) * FCH + f0]) = r;
        }
        if (o + 2 < OUT_LEN) {
            unpack2(a2, v0, v1);
            float2 r; r.x = fmaxf(v0, 0.0f); r.y = fmaxf(v1, 0.0f);
            *reinterpret_cast<float2*>(&outb[(size_t)(o + 2) * FCH + f0]) = r;
        }
        if (o + 3 < OUT_LEN) {
            unpack2(a3, v0, v1);
            float2 r; r.x = fmaxf(v0, 0.0f); r.y = fmaxf(v1, 0.0f);
            *reinterpret_cast<float2*>(&outb[(size_t)(o + 3) * FCH + f0]) = r;
        }
    }
}

extern "C" void kernel_launch(void* const* d_in, const int* in_sizes, int n_in,
                              void* d_out, int out_size) {
    const float* x    = (const float*)d_in[0];   // (64, 16384) fp32
    const float* kern = (const float*)d_in[1];   // (128, 16)  fp32
    float* out        = (float*)d_out;           // (64, 16369, 128) fp32

    dim3 grid((OUT_LEN + TILE_O - 1) / TILE_O, BATCH);   // (128, 64)
    speccnn1d_kernel<<<grid, NTHREADS>>>(x, kern, out);
}

// round 3
// speedup vs baseline: 1.5715x; 1.5715x over previous
#include <cuda_runtime.h>
#include <cstdint>

// Problem constants (fixed by the reference)
#define BATCH    64
#define LSEQ     16384
#define FCH      128
#define KW       16
#define OUT_LEN  16369           // (16384 - 16) + 1
#define TILE_O   64              // output positions per block
#define NTHREADS 256             // 8 warps
#define BO       8               // o positions per inner block
#define XWIN     (BO + KW - 1)   // 23

typedef unsigned long long u64;

// ---------------- packed f32x2 helpers (Blackwell) ----------------
__device__ __forceinline__ u64 pack2(float lo, float hi) {
    u64 r;
    asm("mov.b64 %0, {%1, %2};" : "=l"(r) : "f"(lo), "f"(hi));
    return r;
}
__device__ __forceinline__ void ffma2(u64& d, u64 a, u64 b, u64 c) {
    asm("fma.rn.f32x2 %0, %1, %2, %3;" : "=l"(d) : "l"(a), "l"(b), "l"(c));
}
__device__ __forceinline__ void unpack2(u64 v, float& lo, float& hi) {
    asm("mov.b64 {%0, %1}, %2;" : "=f"(lo), "=f"(hi) : "l"(v));
}

__global__ __launch_bounds__(NTHREADS, 3)
void speccnn1d_kernel(const float* __restrict__ x,
                      const float* __restrict__ kern,
                      float* __restrict__ out) {
    // x window pre-duplicated as {v,v} u64: mainloop is broadcast-LDS.64 -> FFMA2.
    __shared__ u64 xs2[TILE_O + KW];                     // 80 * 8B

    const int tid = threadIdx.x;
    const int b   = blockIdx.y;
    const int o0  = blockIdx.x * TILE_O;

    // ---- stage x window duplicated ----
    {
        const float* xb = x + (size_t)b * LSEQ;
        if (tid < TILE_O + KW - 1) {                     // 79 elements
            int xi = o0 + tid;
            float v = (xi < LSEQ) ? __ldg(&xb[xi]) : 0.0f;
            xs2[tid] = pack2(v, v);
        }
    }

    // Thread -> (channel pair, o-subgroup). og is warp-uniform => broadcast LDS.
    const int f0 = ((tid & 31) << 1) + (((tid >> 5) & 1) << 6);  // even, 0..126
    const int og = tid >> 6;                                     // 0..3

    // ---- hoist this thread's 2 weight rows into 16 packed pairs (32 regs) ----
    u64 w[KW];
    {
        const float4* r0 = reinterpret_cast<const float4*>(kern + (size_t)f0 * KW);
        const float4* r1 = reinterpret_cast<const float4*>(kern + (size_t)(f0 + 1) * KW);
        #pragma unroll
        for (int q = 0; q < 4; q++) {
            float4 a = __ldg(&r0[q]);
            float4 c = __ldg(&r1[q]);
            w[q * 4 + 0] = pack2(a.x, c.x);
            w[q * 4 + 1] = pack2(a.y, c.y);
            w[q * 4 + 2] = pack2(a.z, c.z);
            w[q * 4 + 3] = pack2(a.w, c.w);
        }
    }
    __syncthreads();

    float* outp = out + (size_t)b * OUT_LEN * FCH + f0;

    // ---- two 8-o blocks per thread; diagonal order: each x loaded once ----
    #pragma unroll
    for (int half = 0; half < 2; half++) {
        const int lo = og * (2 * BO) + half * BO;        // local o within tile
        const int o  = o0 + lo;

        u64 acc[BO];
        #pragma unroll
        for (int j = 0; j < BO; j++) acc[j] = 0ull;

        #pragma unroll
        for (int i = 0; i < XWIN; i++) {
            u64 xv = xs2[lo + i];                        // single broadcast LDS.64
            #pragma unroll
            for (int j = 0; j < BO; j++) {
                const int k = i - j;
                if (k >= 0 && k < KW)
                    ffma2(acc[j], xv, w[k], acc[j]);
            }
        }

        float* po = outp + (size_t)o * FCH;
        if (o + BO <= OUT_LEN) {
            // fast path: all 16384 blocks except the very last tile
            #pragma unroll
            for (int j = 0; j < BO; j++) {
                float v0, v1;
                unpack2(acc[j], v0, v1);
                float2 r; r.x = fmaxf(v0, 0.0f); r.y = fmaxf(v1, 0.0f);
                *reinterpret_cast<float2*>(po + j * FCH) = r;
            }
        } else {
            #pragma unroll
            for (int j = 0; j < BO; j++) {
                if (o + j < OUT_LEN) {
                    float v0, v1;
                    unpack2(acc[j], v0, v1);
                    float2 r; r.x = fmaxf(v0, 0.0f); r.y = fmaxf(v1, 0.0f);
                    *reinterpret_cast<float2*>(po + j * FCH) = r;
                }
            }
        }
    }
}

extern "C" void kernel_launch(void* const* d_in, const int* in_sizes, int n_in,
                              void* d_out, int out_size) {
    const float* x    = (const float*)d_in[0];   // (64, 16384) fp32
    const float* kern = (const float*)d_in[1];   // (128, 16)  fp32
    float* out        = (float*)d_out;           // (64, 16369, 128) fp32

    dim3 grid((OUT_LEN + TILE_O - 1) / TILE_O, BATCH);   // (256, 64)
    speccnn1d_kernel<<<grid, NTHREADS>>>(x, kern, out);
}